// round 3
// baseline (speedup 1.0000x reference)
#include <cuda_runtime.h>
#include <cuda_bf16.h>

// PositionOnlyAttention — GB300 sm_103a
//
// Algorithmic collapse of the reference:
//   j*(h,i) = first j with route_table[h, i<<12 | j] != 0   (iid 0/1 -> depth ~2)
//   head bit t = value_table[h,t, pack10(vin[j*][conns_value[h,t,:]])] > 0.5
//   out[i,t]   = output_table[t, pack12(combined[i][conns_out[t,:]])]
//
// One CTA per row i (128 threads). Warp h = head h: int4-ballot route scan
// (128 j per iteration), token row packed into a ballot mask, lanes 0..15 do
// the 16 value-table lookups (conns loaded as int2 pairs). Warp 0 does the
// 16 output lookups (conns loaded as int4 triples) after a block sync.
// Hot data (vtab 256KB + otab 256KB + touched route slice ~1MB) is
// L2-resident across graph replays.

#define S_LEN      2048
#define TOKEN_BITS 16
#define NHEADS     4
#define NPOS       12
#define VBITS      10
#define OBITS      12

__global__ __launch_bounds__(128, 8)
void poa_kernel(const int*   __restrict__ tokens,      // (S,16)
                const int*   __restrict__ route,       // (H, 1<<24)
                const float* __restrict__ vtab,        // (H,16,1024)
                const float* __restrict__ otab,        // (16,4096)
                const int*   __restrict__ cv,          // (H,16,10)
                const int*   __restrict__ co,          // (16,12)
                float*       __restrict__ out)         // (S,16)
{
    const int i    = blockIdx.x;
    const int h    = threadIdx.x >> 5;   // warp id == head
    const int lane = threadIdx.x & 31;

    __shared__ unsigned int comb[NHEADS];

    // ---- route scan: first j in [0,2048) with route[h, i<<12 | j] != 0 ----
    // int4 per lane -> 128 consecutive j per warp iteration.
    const int4* rrow = (const int4*)(route + (((long long)h) << (2 * NPOS))
                                           + ((long long)i << NPOS));
    int jstar = -1;
    for (int j0 = 0; j0 < S_LEN; j0 += 128) {
        int4 v = __ldg(rrow + (j0 >> 2) + lane);
        unsigned any = __ballot_sync(0xFFFFFFFFu,
                                     (v.x | v.y | v.z | v.w) != 0);
        if (any) {
            int src = __ffs(any) - 1;               // first lane with a hit
            int vx = __shfl_sync(0xFFFFFFFFu, v.x, src);
            int vy = __shfl_sync(0xFFFFFFFFu, v.y, src);
            int vz = __shfl_sync(0xFFFFFFFFu, v.z, src);
            int vw = __shfl_sync(0xFFFFFFFFu, v.w, src);
            int off = (vx != 0) ? 0 : (vy != 0) ? 1 : (vz != 0) ? 2 : 3;
            jstar = j0 + src * 4 + off;
            break;
        }
    }
    // jstar is warp-uniform.

    // ---- pack token row of j* into a ballot mask (bit c = tokens[j*,c]) ----
    unsigned tmask = 0;
    if (jstar >= 0) {
        int tb = (lane < TOKEN_BITS) ? __ldg(tokens + jstar * TOKEN_BITS + lane) : 0;
        tmask = __ballot_sync(0xFFFFFFFFu, tb != 0);
    }

    // ---- value lookups: lane t in [0,16) computes head bit t ----
    int outbit = 0;
    if (jstar >= 0 && lane < TOKEN_BITS) {
        const int t = lane;
        // cv row: 10 ints, 40B, every row 8B-aligned -> 5x LDG.64
        const int2* c2 = (const int2*)(cv + (h * TOKEN_BITS + t) * VBITS);
        int cc[VBITS];
        #pragma unroll
        for (int k = 0; k < VBITS / 2; k++) {
            int2 p = __ldg(c2 + k);
            cc[2 * k]     = p.x;
            cc[2 * k + 1] = p.y;
        }
        // vin[j*][cc]: cc<16 -> token bit; else pos bit (j* >> (27-cc)) & 1.
        // Independent ORs (log-depth) instead of a serial shift chain.
        int vaddr = 0;
        #pragma unroll
        for (int k = 0; k < VBITS; k++) {
            int c = cc[k];
            int bit = (c < TOKEN_BITS) ? (int)((tmask >> c) & 1u)
                                       : ((jstar >> (TOKEN_BITS + NPOS - 1 - c)) & 1);
            vaddr |= bit << (VBITS - 1 - k);
        }
        float val = __ldg(vtab + ((h * TOKEN_BITS + t) << VBITS) + vaddr);
        outbit = (val > 0.5f) ? 1 : 0;
    }
    unsigned headbits = __ballot_sync(0xFFFFFFFFu, outbit != 0) & 0xFFFFu;

    if (lane == 0) comb[h] = headbits;
    __syncthreads();

    // ---- output stage: warp 0, lanes 0..15 ----
    if (threadIdx.x < TOKEN_BITS) {
        const int t = threadIdx.x;
        unsigned long long cw =
              (unsigned long long)comb[0]
            | ((unsigned long long)comb[1] << 16)
            | ((unsigned long long)comb[2] << 32)
            | ((unsigned long long)comb[3] << 48);
        // co row: 12 ints, 48B, every row 16B-aligned -> 3x LDG.128
        const int4* c4 = (const int4*)(co + t * OBITS);
        int cc[OBITS];
        #pragma unroll
        for (int k = 0; k < OBITS / 4; k++) {
            int4 q = __ldg(c4 + k);
            cc[4 * k]     = q.x;
            cc[4 * k + 1] = q.y;
            cc[4 * k + 2] = q.z;
            cc[4 * k + 3] = q.w;
        }
        int oaddr = 0;
        #pragma unroll
        for (int k = 0; k < OBITS; k++) {
            oaddr |= (int)((cw >> cc[k]) & 1ULL) << (OBITS - 1 - k);
        }
        out[i * TOKEN_BITS + t] = __ldg(otab + (t << OBITS) + oaddr);
    }
}

extern "C" void kernel_launch(void* const* d_in, const int* in_sizes, int n_in,
                              void* d_out, int out_size) {
    const int*   tokens = (const int*)  d_in[0];  // (2048,16) int32
    const int*   route  = (const int*)  d_in[1];  // (4, 1<<24) int32
    const float* vtab   = (const float*)d_in[2];  // (4,16,1024) f32
    const float* otab   = (const float*)d_in[3];  // (16,4096) f32
    const int*   cv     = (const int*)  d_in[4];  // (4,16,10) int32
    const int*   co     = (const int*)  d_in[5];  // (16,12) int32
    float*       out    = (float*)d_out;          // (2048,16) f32

    poa_kernel<<<S_LEN, 128>>>(tokens, route, vtab, otab, cv, co, out);
}

// round 6
// speedup vs baseline: 1.3077x; 1.3077x over previous
#include <cuda_runtime.h>
#include <cuda_bf16.h>

// PositionOnlyAttention — GB300 sm_103a
//
//   j*(h,i) = first j with route_table[h, i<<12 | j] != 0   (iid 0/1 -> depth ~2)
//   head bit t = value_table[h,t, pack10(vin[j*][conns_value[h,t,:]])] > 0.5
//   out[i,t]   = output_table[t, pack12(combined[i][conns_out[t,:]])]
//
// One CTA per row i (128 threads), warp h = head h.
// vs R3 (8.7us measured, ~4.3MB HBM traffic from the int4 route probe):
//  - route probe is ONE int per lane (32 j window, 1 cache line/warp instead
//    of 4): cuts route DRAM/L2 sector traffic 4x and L1tex queue depth 4x.
//    Fallback loop keeps correctness for pathological rows (P(miss)=2^-32).
//  - conns_value / conns_out index rows are prefetched BEFORE the route scan
//    (independent of j*), overlapping their latency with the scan.

#define S_LEN      2048
#define TOKEN_BITS 16
#define NHEADS     4
#define NPOS       12
#define VBITS      10
#define OBITS      12

__global__ __launch_bounds__(128)
void poa_kernel(const int*   __restrict__ tokens,      // (S,16)
                const int*   __restrict__ route,       // (H, 1<<24)
                const float* __restrict__ vtab,        // (H,16,1024)
                const float* __restrict__ otab,        // (16,4096)
                const int*   __restrict__ cv,          // (H,16,10)
                const int*   __restrict__ co,          // (16,12)
                float*       __restrict__ out)         // (S,16)
{
    const int i    = blockIdx.x;
    const int h    = threadIdx.x >> 5;   // warp id == head
    const int lane = threadIdx.x & 31;

    __shared__ unsigned int comb[NHEADS];

    // ---- prefetch index tables (independent of j*) ----
    // cv row for (h, t=lane): 10 ints = 5x LDG.64 (rows are 8B-aligned)
    int cc[VBITS];
    if (lane < TOKEN_BITS) {
        const int2* c2 = (const int2*)(cv + (h * TOKEN_BITS + lane) * VBITS);
        #pragma unroll
        for (int k = 0; k < VBITS / 2; k++) {
            int2 p = __ldg(c2 + k);
            cc[2 * k]     = p.x;
            cc[2 * k + 1] = p.y;
        }
    }
    // co row for t = threadIdx.x (warp 0 only): 12 ints = 3x LDG.128
    int oc[OBITS];
    if (threadIdx.x < TOKEN_BITS) {
        const int4* c4 = (const int4*)(co + threadIdx.x * OBITS);
        #pragma unroll
        for (int k = 0; k < OBITS / 4; k++) {
            int4 q = __ldg(c4 + k);
            oc[4 * k]     = q.x;
            oc[4 * k + 1] = q.y;
            oc[4 * k + 2] = q.z;
            oc[4 * k + 3] = q.w;
        }
    }

    // ---- route scan: first j in [0,2048) with route[h, i<<12 | j] != 0 ----
    // One int per lane -> 32 j per iteration, 1 cache line per warp.
    const int* rrow = route + (((long long)h) << (2 * NPOS)) + ((long long)i << NPOS);
    int jstar = -1;
    for (int j0 = 0; j0 < S_LEN; j0 += 32) {
        int v = __ldg(rrow + j0 + lane);
        unsigned m = __ballot_sync(0xFFFFFFFFu, v != 0);
        if (m) { jstar = j0 + __ffs(m) - 1; break; }
    }
    // jstar is warp-uniform.

    // ---- pack token row of j* into a ballot mask (bit c = tokens[j*,c]) ----
    unsigned tmask = 0;
    if (jstar >= 0) {
        int tb = (lane < TOKEN_BITS) ? __ldg(tokens + jstar * TOKEN_BITS + lane) : 0;
        tmask = __ballot_sync(0xFFFFFFFFu, tb != 0);
    }

    // ---- value lookups: lane t in [0,16) computes head bit t ----
    int outbit = 0;
    if (jstar >= 0 && lane < TOKEN_BITS) {
        const int t = lane;
        // vin[j*][c]: c<16 -> token bit; else pos bit (j* >> (27-c)) & 1.
        int vaddr = 0;
        #pragma unroll
        for (int k = 0; k < VBITS; k++) {
            int c = cc[k];
            int bit = (c < TOKEN_BITS) ? (int)((tmask >> c) & 1u)
                                       : ((jstar >> (TOKEN_BITS + NPOS - 1 - c)) & 1);
            vaddr |= bit << (VBITS - 1 - k);
        }
        float val = __ldg(vtab + ((h * TOKEN_BITS + t) << VBITS) + vaddr);
        outbit = (val > 0.5f) ? 1 : 0;
    }
    unsigned headbits = __ballot_sync(0xFFFFFFFFu, outbit != 0) & 0xFFFFu;

    if (lane == 0) comb[h] = headbits;
    __syncthreads();

    // ---- output stage: warp 0, lanes 0..15 ----
    if (threadIdx.x < TOKEN_BITS) {
        const int t = threadIdx.x;
        unsigned long long cw =
              (unsigned long long)comb[0]
            | ((unsigned long long)comb[1] << 16)
            | ((unsigned long long)comb[2] << 32)
            | ((unsigned long long)comb[3] << 48);
        int oaddr = 0;
        #pragma unroll
        for (int k = 0; k < OBITS; k++) {
            oaddr |= (int)((cw >> oc[k]) & 1ULL) << (OBITS - 1 - k);
        }
        out[i * TOKEN_BITS + t] = __ldg(otab + (t << OBITS) + oaddr);
    }
}

extern "C" void kernel_launch(void* const* d_in, const int* in_sizes, int n_in,
                              void* d_out, int out_size) {
    const int*   tokens = (const int*)  d_in[0];  // (2048,16) int32
    const int*   route  = (const int*)  d_in[1];  // (4, 1<<24) int32
    const float* vtab   = (const float*)d_in[2];  // (4,16,1024) f32
    const float* otab   = (const float*)d_in[3];  // (16,4096) f32
    const int*   cv     = (const int*)  d_in[4];  // (4,16,10) int32
    const int*   co     = (const int*)  d_in[5];  // (16,12) int32
    float*       out    = (float*)d_out;          // (2048,16) f32

    poa_kernel<<<S_LEN, 128>>>(tokens, route, vtab, otab, cv, co, out);
}